// round 16
// baseline (speedup 1.0000x reference)
#include <cuda_runtime.h>
#include <cuda_fp16.h>
#include <cstdint>

// STFT via hop-polyphase + one radix-2 DIT level + freq-domain hann.
//   E_k, O_k = 256-pt DFTs (1024-periodic) of even/odd samples, same weights.
//   U_k = E_k + w^k O_k, k=0..512; U_{1024-k} = conj(E_k - w^k O_k).
//   GEMM: CTA 64m x 128j, K=256, dual acc (E,O), warp tile 32x32, U fp16.
//   Epilogue butterfly in registers via shfl_xor(4) (partner row = lane^4).
//   Combine: X_t[k] = sum_q (-i)^{kq} U_{t+q}[k]; F = 0.5X - 0.25(X[k-1]+X[k+1]).
//   NOTE: out pitch NT=513 is odd -> direct vector STG misaligned; stores go
//   through the smem re-coalescing bounce.

#define KF     1025
#define NBC    32
#define LEN    262144
#define NT     513
#define NSEG   516
#define NJ     (NBC * NSEG)      // 16512
#define MROWSA 1152
#define KHALF  256
#define NITER  4                 // KHALF / 64
#define IMAG_OFF 16826400L

__device__ __half g_A[(size_t)MROWSA * KHALF];
__device__ __half g_B[(size_t)NJ * 512];        // [j][c]: c<256 even, else odd
__device__ __half g_Uh[(size_t)2050 * NJ + 32]; // rows 0..1024 re, 1025..2049 im (+pad)
__device__ float  g_cos_tab[2048];
__device__ float  g_msin_tab[2048];

#define SW128(b) ((b) ^ (((b) >> 3) & 0x70))

// ============================ fused prep: pack_b + pack_a + tables ============================
#define PREP_PB (NJ / 2)          // 8256
#define PREP_PA 576
#define PREP_GRID (PREP_PB + PREP_PA + 8)

__global__ void prep_kernel(const float* __restrict__ x) {
    const int b = blockIdx.x;
    const int tid = threadIdx.x;
    if (b < PREP_PB) {
        int j  = 2 * b + (tid >> 7);
        int bc = j / NSEG;
        int s  = j - bc * NSEG;
        const float* xbc = x + (size_t)bc * LEN;
        __half* bj = g_B + (size_t)j * 512;
        int c4 = tid & 127;
        int p0 = s * 512 - 1024 + 4 * c4;
        float4 v;
        if (s >= 2 && s <= 513) {
            v = *(const float4*)(xbc + p0);
        } else {
            float tmp[4];
#pragma unroll
            for (int e = 0; e < 4; ++e) {
                int p = p0 + e;
                if (p < 0) p = -p;
                if (p >= LEN) p = 2 * LEN - 2 - p;
                tmp[e] = xbc[p];
            }
            v = make_float4(tmp[0], tmp[1], tmp[2], tmp[3]);
        }
        *(__half2*)&bj[2 * c4]       = __floats2half2_rn(v.x, v.z);
        *(__half2*)&bj[256 + 2 * c4] = __floats2half2_rn(v.y, v.w);
    } else if (b < PREP_PB + PREP_PA) {
        int idx2 = ((b - PREP_PB) * 256 + tid) * 2;
        int m = idx2 >> 8;
        int c = idx2 & 255;
        __half o[2];
        if (m < 1026) {
            int k = m >> 1;
            if (m & 1) {
                o[0] = __float2half_rn(-sinpif((float)((2 * k * c) & 2047) * (1.0f / 1024.0f)));
                o[1] = __float2half_rn(-sinpif((float)((2 * k * (c + 1)) & 2047) * (1.0f / 1024.0f)));
            } else {
                o[0] = __float2half_rn(cospif((float)((2 * k * c) & 2047) * (1.0f / 1024.0f)));
                o[1] = __float2half_rn(cospif((float)((2 * k * (c + 1)) & 2047) * (1.0f / 1024.0f)));
            }
        } else {
            o[0] = o[1] = __float2half_rn(0.f);
        }
        *(__half2*)&g_A[(size_t)m * KHALF + c] = *(__half2*)o;
    } else {
        int i = (b - PREP_PB - PREP_PA) * 256 + tid;
        float a = (float)i * (1.0f / 1024.0f);
        g_cos_tab[i]  = cospif(a);
        g_msin_tab[i] = -sinpif(a);
    }
}

// ============================ GEMM (mma.sync fp16, dual-acc E/O) ============================
#define CP16(dst, src) \
    asm volatile("cp.async.cg.shared.global [%0], [%1], 16;" :: "r"(dst), "l"(src))
#define CP_COMMIT() asm volatile("cp.async.commit_group;" ::: "memory")
#define CP_WAIT1()  asm volatile("cp.async.wait_group 1;" ::: "memory")
#define CP_WAIT0()  asm volatile("cp.async.wait_group 0;" ::: "memory")

__device__ __forceinline__ uint32_t smem_u32(const void* p) {
    uint32_t a;
    asm("{ .reg .u64 t; cvta.to.shared.u64 t, %1; cvt.u32.u64 %0, t; }"
        : "=r"(a) : "l"(p));
    return a;
}
__device__ __forceinline__ void ldsm4(uint32_t* r, uint32_t addr) {
    asm volatile("ldmatrix.sync.aligned.m8n8.x4.shared.b16 {%0,%1,%2,%3}, [%4];"
                 : "=r"(r[0]), "=r"(r[1]), "=r"(r[2]), "=r"(r[3]) : "r"(addr));
}
__device__ __forceinline__ void mma16816(float* d, const uint32_t* a, const uint32_t* b) {
    asm volatile(
        "mma.sync.aligned.m16n8k16.row.col.f32.f16.f16.f32 "
        "{%0,%1,%2,%3},{%4,%5,%6,%7},{%8,%9},{%0,%1,%2,%3};"
        : "+f"(d[0]), "+f"(d[1]), "+f"(d[2]), "+f"(d[3])
        : "r"(a[0]), "r"(a[1]), "r"(a[2]), "r"(a[3]), "r"(b[0]), "r"(b[1]));
}

#define A_BYTES    8192
#define BT_BYTES   16384
#define STAGE_BYTES 40960
#define GEMM_SMEM  (2 * STAGE_BYTES)

__global__ void __launch_bounds__(256, 2) gemm_mma_kernel() {
    extern __shared__ char smem[];
    const int tid = threadIdx.x;
    const int wid = tid >> 5;
    const int lane = tid & 31;
    const int m0 = blockIdx.y * 64;
    const int j0 = blockIdx.x * 128;

    const uint32_t sbase = smem_u32(smem);

    uint32_t aoff[2], boff[4];
    const __half* gAp[2];
    const __half* gBep[4];
    const __half* gBop[4];
#pragma unroll
    for (int q = 0; q < 2; ++q) {
        int chunk = tid + q * 256;
        int row = chunk >> 3, slot = chunk & 7;
        aoff[q] = SW128((uint32_t)row * 128 + slot * 16);
        gAp[q] = g_A + (size_t)(m0 + row) * KHALF + slot * 8;
    }
#pragma unroll
    for (int q = 0; q < 4; ++q) {
        int chunk = tid + q * 256;
        int row = chunk >> 3, slot = chunk & 7;
        boff[q] = SW128((uint32_t)row * 128 + slot * 16);
        gBep[q] = g_B + (size_t)(j0 + row) * 512 + slot * 8;
        gBop[q] = gBep[q] + 256;
    }

#define ISSUE_LOAD(it, buf) do {                                               \
    uint32_t _b = sbase + (buf) * STAGE_BYTES;                                 \
    _Pragma("unroll")                                                          \
    for (int q = 0; q < 2; ++q) CP16(_b + aoff[q], gAp[q] + (it) * 64);        \
    _Pragma("unroll")                                                          \
    for (int q = 0; q < 4; ++q) {                                              \
        CP16(_b + A_BYTES + boff[q],            gBep[q] + (it) * 64);          \
        CP16(_b + A_BYTES + BT_BYTES + boff[q], gBop[q] + (it) * 64);          \
    }                                                                          \
} while (0)

    const int wm = wid >> 2;
    const int wn = wid & 3;
    const int arow = wm * 32 + (lane & 15);
    const int abyt = (lane >> 4) * 16;
    const int brow = wn * 32 + ((lane >> 4) << 3) + (lane & 7);
    const int bbyt = ((lane >> 3) & 1) * 16;

    float accE[2][4][4], accO[2][4][4];
#pragma unroll
    for (int i = 0; i < 2; ++i)
#pragma unroll
        for (int jt = 0; jt < 4; ++jt)
#pragma unroll
            for (int e = 0; e < 4; ++e) { accE[i][jt][e] = 0.f; accO[i][jt][e] = 0.f; }

    ISSUE_LOAD(0, 0); CP_COMMIT();
    ISSUE_LOAD(1, 1); CP_COMMIT();

    for (int it = 0; it < NITER; ++it) {
        if (it < NITER - 1) CP_WAIT1(); else CP_WAIT0();
        __syncthreads();

        const uint32_t bA = sbase + (it & 1) * STAGE_BYTES;
        const uint32_t bE = bA + A_BYTES;
        const uint32_t bO = bE + BT_BYTES;
#pragma unroll
        for (int s = 0; s < 4; ++s) {
            uint32_t a[2][4], be[2][4], bo[2][4];
#pragma unroll
            for (int i = 0; i < 2; ++i)
                ldsm4(a[i], bA + SW128((uint32_t)(arow + i * 16) * 128 + s * 32 + abyt));
#pragma unroll
            for (int p = 0; p < 2; ++p) {
                ldsm4(be[p], bE + SW128((uint32_t)(brow + p * 16) * 128 + s * 32 + bbyt));
                ldsm4(bo[p], bO + SW128((uint32_t)(brow + p * 16) * 128 + s * 32 + bbyt));
            }
#pragma unroll
            for (int i = 0; i < 2; ++i) {
#pragma unroll
                for (int p = 0; p < 2; ++p) {
                    mma16816(accE[i][2 * p],     a[i], &be[p][0]);
                    mma16816(accE[i][2 * p + 1], a[i], &be[p][2]);
                    mma16816(accO[i][2 * p],     a[i], &bo[p][0]);
                    mma16816(accO[i][2 * p + 1], a[i], &bo[p][2]);
                }
            }
        }

        if (it < NITER - 1) {
            __syncthreads();
            if (it + 2 < NITER) { ISSUE_LOAD(it + 2, it & 1); CP_COMMIT(); }
        }
    }

    // ---- epilogue: register butterfly via shfl_xor(4), direct half2 stores ----
    // Thread holds rows R1 = wm*32 + i*16 + (lane>>2) and R2 = R1+8 (same parity).
    // Even-parity rows = cos rows (real), odd = -sin rows (imag).
    // Partner row R^1 lives in lane^4 at the same (i, jt, e).
    const int rq   = lane >> 2;          // 0..7
    const int rpar = rq & 1;             // 0: holds real rows; 1: holds imag rows
    const int jc   = j0 + wn * 32 + (lane & 3) * 2;

#pragma unroll
    for (int i = 0; i < 2; ++i) {
        // k indices for the two row-pairs this thread touches
        const int kgA = (m0 + wm * 32 + i * 16 + (rq & ~1)) >> 1;   // rows R1, R1^1
        const int kgB = kgA + 4;                                    // rows R2, R2^1
        const float cwA = g_cos_tab[kgA],  swA = g_msin_tab[kgA];
        const float cwB = g_cos_tab[kgB],  swB = g_msin_tab[kgB];
        const int krowA = rpar ? (1024 - kgA) : kgA;
        const int krowB = rpar ? (1024 - kgB) : kgB;
#pragma unroll
        for (int jt = 0; jt < 4; ++jt) {
            float myE[4], myO[4], otE[4], otO[4];
#pragma unroll
            for (int e = 0; e < 4; ++e) {
                myE[e] = accE[i][jt][e];
                myO[e] = accO[i][jt][e];
                otE[e] = __shfl_xor_sync(0xffffffffu, myE[e], 4);
                otO[e] = __shfl_xor_sync(0xffffffffu, myO[e], 4);
            }
            // row-pair A: elements e=0,1 (cols jc, jc+1)
            if (kgA <= 512) {
                float er0 = rpar ? otE[0] : myE[0], er1 = rpar ? otE[1] : myE[1];
                float ei0 = rpar ? myE[0] : otE[0], ei1 = rpar ? myE[1] : otE[1];
                float or0 = rpar ? otO[0] : myO[0], or1 = rpar ? otO[1] : myO[1];
                float oi0 = rpar ? myO[0] : otO[0], oi1 = rpar ? myO[1] : otO[1];
                float pr0 = cwA * or0 - swA * oi0, pi0 = cwA * oi0 + swA * or0;
                float pr1 = cwA * or1 - swA * oi1, pi1 = cwA * oi1 + swA * or1;
                float re0 = rpar ? (er0 - pr0) : (er0 + pr0);
                float re1 = rpar ? (er1 - pr1) : (er1 + pr1);
                float im0 = rpar ? (pi0 - ei0) : (ei0 + pi0);
                float im1 = rpar ? (pi1 - ei1) : (ei1 + pi1);
                size_t jgoff = (size_t)jc + jt * 8;
                *(__half2*)(g_Uh + (size_t)krowA * NJ + jgoff)        = __floats2half2_rn(re0, re1);
                *(__half2*)(g_Uh + (size_t)(KF + krowA) * NJ + jgoff) = __floats2half2_rn(im0, im1);
            }
            // row-pair B: elements e=2,3
            if (kgB <= 512) {
                float er0 = rpar ? otE[2] : myE[2], er1 = rpar ? otE[3] : myE[3];
                float ei0 = rpar ? myE[2] : otE[2], ei1 = rpar ? myE[3] : otE[3];
                float or0 = rpar ? otO[2] : myO[2], or1 = rpar ? otO[3] : myO[3];
                float oi0 = rpar ? myO[2] : otO[2], oi1 = rpar ? myO[3] : otO[3];
                float pr0 = cwB * or0 - swB * oi0, pi0 = cwB * oi0 + swB * or0;
                float pr1 = cwB * or1 - swB * oi1, pi1 = cwB * oi1 + swB * or1;
                float re0 = rpar ? (er0 - pr0) : (er0 + pr0);
                float re1 = rpar ? (er1 - pr1) : (er1 + pr1);
                float im0 = rpar ? (pi0 - ei0) : (ei0 + pi0);
                float im1 = rpar ? (pi1 - ei1) : (ei1 + pi1);
                size_t jgoff = (size_t)jc + jt * 8;
                *(__half2*)(g_Uh + (size_t)krowB * NJ + jgoff)        = __floats2half2_rn(re0, re1);
                *(__half2*)(g_Uh + (size_t)(KF + krowB) * NJ + jgoff) = __floats2half2_rn(im0, im1);
            }
        }
    }
}

// ============================ combine (4 t's per lane, shfl halo, smem bounce) ============================
__device__ __forceinline__ void unpack8(uint2 a, uint2 b, float* d) {
    float2 f;
    f = __half22float2(*(__half2*)&a.x); d[0] = f.x; d[1] = f.y;
    f = __half22float2(*(__half2*)&a.y); d[2] = f.x; d[3] = f.y;
    f = __half22float2(*(__half2*)&b.x); d[4] = f.x; d[5] = f.y;
    f = __half22float2(*(__half2*)&b.y); d[6] = f.x; d[7] = f.y;
}

__global__ void __launch_bounds__(128) combine5_kernel(float* __restrict__ out) {
    __shared__ float sfr[4][2][128];
    __shared__ float sfi[4][2][128];
    const int bc   = blockIdx.z;
    const int lane = threadIdx.x;
    const int ty   = threadIdx.y;
    const int tbase = blockIdx.x * 128;
    const int kb   = (blockIdx.y * 4 + ty) * 32;
    if (kb > 1024) return;

    const int t4  = tbase + lane * 4;
    const int tt4 = (t4 <= 512) ? t4 : 512;
    const size_t jj = (size_t)bc * NSEG + tt4;
    const long baseT = (long)bc * KF;

    float pXr0[4], pXr1[4], pXi0[4], pXi1[4];
#pragma unroll
    for (int e = 0; e < 4; ++e) { pXr0[e] = pXr1[e] = pXi0[e] = pXi1[e] = 0.f; }

#pragma unroll 2
    for (int i = 0; i < 34; ++i) {
        int k = kb - 1 + i;
        int kk = k;
        float sgn = 1.f;
        if (kk < 0)         { kk = -kk;       sgn = -1.f; }
        else if (kk > 1024) { kk = 2048 - kk; sgn = -1.f; }

        const __half* pr = g_Uh + (size_t)kk * NJ + jj;
        const __half* pi = g_Uh + (size_t)(KF + kk) * NJ + jj;
        uint2 vr_ = *(const uint2*)pr;
        uint2 vi_ = *(const uint2*)pi;
        uint2 vrn, vin;
        vrn.x = __shfl_down_sync(0xffffffffu, vr_.x, 1);
        vrn.y = __shfl_down_sync(0xffffffffu, vr_.y, 1);
        vin.x = __shfl_down_sync(0xffffffffu, vi_.x, 1);
        vin.y = __shfl_down_sync(0xffffffffu, vi_.y, 1);
        if (lane == 31) {
            vrn = *(const uint2*)(pr + 4);
            vin = *(const uint2*)(pi + 4);
        }
        float rr[8], ii[8];
        unpack8(vr_, vrn, rr);
        unpack8(vi_, vin, ii);

        float xr[4], xi[4];
        switch (kk & 3) {
            case 0:
#pragma unroll
                for (int e = 0; e < 4; ++e) {
                    xr[e] = rr[e] + rr[e+1] + rr[e+2] + rr[e+3];
                    xi[e] = sgn * (ii[e] + ii[e+1] + ii[e+2] + ii[e+3]);
                }
                break;
            case 1:
#pragma unroll
                for (int e = 0; e < 4; ++e) {
                    xr[e] = rr[e] + ii[e+1] - rr[e+2] - ii[e+3];
                    xi[e] = sgn * (ii[e] - rr[e+1] - ii[e+2] + rr[e+3]);
                }
                break;
            case 2:
#pragma unroll
                for (int e = 0; e < 4; ++e) {
                    xr[e] = rr[e] - rr[e+1] + rr[e+2] - rr[e+3];
                    xi[e] = sgn * (ii[e] - ii[e+1] + ii[e+2] - ii[e+3]);
                }
                break;
            default:
#pragma unroll
                for (int e = 0; e < 4; ++e) {
                    xr[e] = rr[e] - ii[e+1] - rr[e+2] + ii[e+3];
                    xi[e] = sgn * (ii[e] + rr[e+1] - ii[e+2] - rr[e+3]);
                }
                break;
        }

        if (i >= 2) {
            const int ko = k - 1;
            const int buf = i & 1;
            float4 vr, vi;
            vr.x = 0.5f * pXr1[0] - 0.25f * (pXr0[0] + xr[0]);
            vr.y = 0.5f * pXr1[1] - 0.25f * (pXr0[1] + xr[1]);
            vr.z = 0.5f * pXr1[2] - 0.25f * (pXr0[2] + xr[2]);
            vr.w = 0.5f * pXr1[3] - 0.25f * (pXr0[3] + xr[3]);
            vi.x = 0.5f * pXi1[0] - 0.25f * (pXi0[0] + xi[0]);
            vi.y = 0.5f * pXi1[1] - 0.25f * (pXi0[1] + xi[1]);
            vi.z = 0.5f * pXi1[2] - 0.25f * (pXi0[2] + xi[2]);
            vi.w = 0.5f * pXi1[3] - 0.25f * (pXi0[3] + xi[3]);
            *(float4*)&sfr[ty][buf][lane * 4] = vr;
            *(float4*)&sfi[ty][buf][lane * 4] = vi;
            __syncwarp();
            if (ko <= 1024) {
                const long baseR = (baseT + ko) * NT;
#pragma unroll
                for (int e = 0; e < 4; ++e) {
                    int t = tbase + 32 * e + lane;
                    if (t <= 512) {
                        out[baseR + t]            = sfr[ty][buf][32 * e + lane];
                        out[IMAG_OFF + baseR + t] = sfi[ty][buf][32 * e + lane];
                    }
                }
            }
        }
#pragma unroll
        for (int e = 0; e < 4; ++e) {
            pXr0[e] = pXr1[e]; pXr1[e] = xr[e];
            pXi0[e] = pXi1[e]; pXi1[e] = xi[e];
        }
    }
}

// ============================ launch ============================
extern "C" void kernel_launch(void* const* d_in, const int* in_sizes, int n_in,
                              void* d_out, int out_size)
{
    const float* x = (const float*)d_in[0];
    float* out = (float*)d_out;

    cudaFuncSetAttribute(gemm_mma_kernel,
                         cudaFuncAttributeMaxDynamicSharedMemorySize, GEMM_SMEM);

    prep_kernel<<<PREP_GRID, 256>>>(x);
    gemm_mma_kernel<<<dim3(NJ / 128, 17), 256, GEMM_SMEM>>>();
    combine5_kernel<<<dim3(5, 9, NBC), dim3(32, 4)>>>(out);
}

// round 17
// speedup vs baseline: 1.0382x; 1.0382x over previous
#include <cuda_runtime.h>
#include <cuda_fp16.h>
#include <cstdint>

// STFT via hop-polyphase + radix-4 DIT + freq-domain hann.
//   S_p[k] = sum_c x[4c+p] e^{-2pi i k c/512}, p=0..3, 512-periodic,
//   S_p[512-k] = conj(S_p[k])  ->  store k=0..256 only.
//   U_kk = sum_p W(kk)^p * S~_p,  W(kk) = e^{-i pi kk/1024},
//   kk in {k', 512-k', 512+k', 1024-k'} all reconstructed from S_p[k'].
//   GEMM: M=576 (pad of 514), K=128, 4 shared-A acc sets; CTA 64m x 64j.
//   U stored fp16 (layout identical to previous rounds); combine unchanged:
//   X_t[k] = sum_q (-i)^{kq} U_{t+q}[k]; F = 0.5X - 0.25(X[k-1]+X[k+1]).
//   NOTE: out pitch NT=513 odd -> direct vector STG misaligned; stores go
//   through the smem re-coalescing bounce.

#define KF     1025
#define NBC    32
#define LEN    262144
#define NT     513
#define NSEG   516
#define NJ     (NBC * NSEG)      // 16512
#define MROWSA 576               // 9 * 64; rows 0..513 = (cos,-sin) k'=0..256
#define KQ     128
#define NITER  2                 // KQ / 64
#define IMAG_OFF 16826400L

__device__ __half g_A[(size_t)MROWSA * KQ];
__device__ __half g_B[(size_t)NJ * 512];        // [j][p*128 + c], x[4c+p]
__device__ __half g_Uh[(size_t)2050 * NJ + 32]; // rows 0..1024 re, 1025..2049 im (+pad)
__device__ float  g_cos_tab[2048];
__device__ float  g_msin_tab[2048];

#define SW128(b) ((b) ^ (((b) >> 3) & 0x70))

// ============================ fused prep: pack_b + pack_a + tables ============================
#define PREP_PB (NJ / 2)          // 8256
#define PREP_PA 144               // 576*128/2/256
#define PREP_GRID (PREP_PB + PREP_PA + 8)

__global__ void prep_kernel(const float* __restrict__ x) {
    const int b = blockIdx.x;
    const int tid = threadIdx.x;
    if (b < PREP_PB) {
        int j  = 2 * b + (tid >> 7);
        int bc = j / NSEG;
        int s  = j - bc * NSEG;
        const float* xbc = x + (size_t)bc * LEN;
        __half* bj = g_B + (size_t)j * 512;
        int c4 = tid & 127;                     // c index; samples 4c4+p
        int p0 = s * 512 - 1024 + 4 * c4;
        float4 v;
        if (s >= 2 && s <= 513) {
            v = *(const float4*)(xbc + p0);
        } else {
            float tmp[4];
#pragma unroll
            for (int e = 0; e < 4; ++e) {
                int p = p0 + e;
                if (p < 0) p = -p;
                if (p >= LEN) p = 2 * LEN - 2 - p;
                tmp[e] = xbc[p];
            }
            v = make_float4(tmp[0], tmp[1], tmp[2], tmp[3]);
        }
        bj[c4]       = __float2half_rn(v.x);    // p=0
        bj[128 + c4] = __float2half_rn(v.y);    // p=1
        bj[256 + c4] = __float2half_rn(v.z);    // p=2
        bj[384 + c4] = __float2half_rn(v.w);    // p=3
    } else if (b < PREP_PB + PREP_PA) {
        int idx2 = ((b - PREP_PB) * 256 + tid) * 2;
        int m = idx2 >> 7;
        int c = idx2 & 127;
        __half o[2];
        if (m < 514) {
            int k = m >> 1;
            if (m & 1) {
                o[0] = __float2half_rn(-sinpif((float)((4 * k * c) & 2047) * (1.0f / 1024.0f)));
                o[1] = __float2half_rn(-sinpif((float)((4 * k * (c + 1)) & 2047) * (1.0f / 1024.0f)));
            } else {
                o[0] = __float2half_rn(cospif((float)((4 * k * c) & 2047) * (1.0f / 1024.0f)));
                o[1] = __float2half_rn(cospif((float)((4 * k * (c + 1)) & 2047) * (1.0f / 1024.0f)));
            }
        } else {
            o[0] = o[1] = __float2half_rn(0.f);
        }
        *(__half2*)&g_A[(size_t)m * KQ + c] = *(__half2*)o;
    } else {
        int i = (b - PREP_PB - PREP_PA) * 256 + tid;
        float a = (float)i * (1.0f / 1024.0f);
        g_cos_tab[i]  = cospif(a);
        g_msin_tab[i] = -sinpif(a);
    }
}

// ============================ GEMM (mma.sync fp16, quad-acc S0..S3) ============================
#define CP16(dst, src) \
    asm volatile("cp.async.cg.shared.global [%0], [%1], 16;" :: "r"(dst), "l"(src))
#define CP_COMMIT() asm volatile("cp.async.commit_group;" ::: "memory")
#define CP_WAIT1()  asm volatile("cp.async.wait_group 1;" ::: "memory")
#define CP_WAIT0()  asm volatile("cp.async.wait_group 0;" ::: "memory")

__device__ __forceinline__ uint32_t smem_u32(const void* p) {
    uint32_t a;
    asm("{ .reg .u64 t; cvta.to.shared.u64 t, %1; cvt.u32.u64 %0, t; }"
        : "=r"(a) : "l"(p));
    return a;
}
__device__ __forceinline__ void ldsm4(uint32_t* r, uint32_t addr) {
    asm volatile("ldmatrix.sync.aligned.m8n8.x4.shared.b16 {%0,%1,%2,%3}, [%4];"
                 : "=r"(r[0]), "=r"(r[1]), "=r"(r[2]), "=r"(r[3]) : "r"(addr));
}
__device__ __forceinline__ void mma16816(float* d, const uint32_t* a, const uint32_t* b) {
    asm volatile(
        "mma.sync.aligned.m16n8k16.row.col.f32.f16.f16.f32 "
        "{%0,%1,%2,%3},{%4,%5,%6,%7},{%8,%9},{%0,%1,%2,%3};"
        : "+f"(d[0]), "+f"(d[1]), "+f"(d[2]), "+f"(d[3])
        : "r"(a[0]), "r"(a[1]), "r"(a[2]), "r"(a[3]), "r"(b[0]), "r"(b[1]));
}

// Stage: A 64x128B (8KB) @0, B sets p=0..3 @8192 + p*8192 (8KB each).
#define A_BYTES    8192
#define BSET_BYTES 8192
#define STAGE_BYTES 40960
#define GEMM_SMEM  (2 * STAGE_BYTES)   // 81920; 2 CTAs/SM; epilogue needs 67584

__global__ void __launch_bounds__(256, 2) gemm_mma_kernel() {
    extern __shared__ char smem[];
    const int tid = threadIdx.x;
    const int wid = tid >> 5;        // 0..7
    const int lane = tid & 31;
    const int m0 = blockIdx.y * 64;  // A-row base (= 2*k' base)
    const int j0 = blockIdx.x * 64;

    const uint32_t sbase = smem_u32(smem);

    // ---- loader mappings ----
    // A: 512 16B-chunks (2/thread). B: 2048 chunks (8/thread), set = chunk>>9.
    uint32_t aoff[2], boff[8];
    const __half* gAp[2];
    const __half* gBp[8];
#pragma unroll
    for (int q = 0; q < 2; ++q) {
        int chunk = tid + q * 256;
        int row = chunk >> 3, slot = chunk & 7;
        aoff[q] = SW128((uint32_t)row * 128 + slot * 16);
        gAp[q] = g_A + (size_t)(m0 + row) * KQ + slot * 8;
    }
#pragma unroll
    for (int q = 0; q < 8; ++q) {
        int chunk = tid + q * 256;
        int set = chunk >> 9;
        int c9  = chunk & 511;
        int row = c9 >> 3, slot = c9 & 7;
        boff[q] = A_BYTES + set * BSET_BYTES + SW128((uint32_t)row * 128 + slot * 16);
        gBp[q] = g_B + (size_t)(j0 + row) * 512 + set * 128 + slot * 8;
    }

#define ISSUE_LOAD(it, buf) do {                                               \
    uint32_t _b = sbase + (buf) * STAGE_BYTES;                                 \
    _Pragma("unroll")                                                          \
    for (int q = 0; q < 2; ++q) CP16(_b + aoff[q], gAp[q] + (it) * 64);        \
    _Pragma("unroll")                                                          \
    for (int q = 0; q < 8; ++q) CP16(_b + boff[q], gBp[q] + (it) * 64);        \
} while (0)

    // ---- warp grid 4(m) x 2(n); warp tile 16m x 32j ----
    const int wm = wid >> 1;         // 0..3
    const int wn = wid & 1;          // 0..1
    const int arow = wm * 16 + (lane & 15);
    const int abyt = (lane >> 4) * 16;
    const int brow = wn * 32 + ((lane >> 4) << 3) + (lane & 7);
    const int bbyt = ((lane >> 3) & 1) * 16;

    float acc[4][4][4];              // [set][jt][e]
#pragma unroll
    for (int p = 0; p < 4; ++p)
#pragma unroll
        for (int jt = 0; jt < 4; ++jt)
#pragma unroll
            for (int e = 0; e < 4; ++e) acc[p][jt][e] = 0.f;

    ISSUE_LOAD(0, 0); CP_COMMIT();
    ISSUE_LOAD(1, 1); CP_COMMIT();

    for (int it = 0; it < NITER; ++it) {
        if (it < NITER - 1) CP_WAIT1(); else CP_WAIT0();
        __syncthreads();

        const uint32_t bA = sbase + (it & 1) * STAGE_BYTES;
#pragma unroll
        for (int s = 0; s < 4; ++s) {
            uint32_t a[4];
            ldsm4(a, bA + SW128((uint32_t)arow * 128 + s * 32 + abyt));
#pragma unroll
            for (int p = 0; p < 4; ++p) {
                const uint32_t bB = bA + A_BYTES + p * BSET_BYTES;
#pragma unroll
                for (int pp = 0; pp < 2; ++pp) {
                    uint32_t bfr[4];
                    ldsm4(bfr, bB + SW128((uint32_t)(brow + pp * 16) * 128 + s * 32 + bbyt));
                    mma16816(acc[p][2 * pp],     a, &bfr[0]);
                    mma16816(acc[p][2 * pp + 1], a, &bfr[2]);
                }
            }
        }
        __syncthreads();   // safe reuse / next stage visibility
    }

    // ---- epilogue: stage S to smem, reconstruct 4 U rows per k', fp16 stores ----
    float* smS = (float*)smem;       // [4][64][66] floats = 67584 B
    {
        const int r1 = wm * 16 + (lane >> 2);
        const int c0 = wn * 32 + (lane & 3) * 2;
#pragma unroll
        for (int p = 0; p < 4; ++p) {
            float* sp = smS + p * (64 * 66);
#pragma unroll
            for (int jt = 0; jt < 4; ++jt) {
                int c = c0 + jt * 8;
                *(float2*)&sp[r1 * 66 + c]       = make_float2(acc[p][jt][0], acc[p][jt][1]);
                *(float2*)&sp[(r1 + 8) * 66 + c] = make_float2(acc[p][jt][2], acc[p][jt][3]);
            }
        }
    }
    __syncthreads();

    // warp wid -> k'locs wid*4 .. wid*4+3; lane -> 2 j's
    const int jl = lane * 2;
    const size_t jg = (size_t)j0 + jl;
#pragma unroll
    for (int h = 0; h < 4; ++h) {
        int kloc = wid * 4 + h;              // 0..31
        int kg = (m0 >> 1) + kloc;           // k'
        if (kg > 256) break;                 // warp-uniform (padding rows)

        float2 Sr[4], Si[4];
#pragma unroll
        for (int p = 0; p < 4; ++p) {
            const float* sp = smS + p * (64 * 66);
            Sr[p] = *(const float2*)&sp[(2 * kloc) * 66 + jl];
            Si[p] = *(const float2*)&sp[(2 * kloc + 1) * 66 + jl];
        }

        // four output rows from this k'
        int kks[4]  = { kg, 512 - kg, 512 + kg, 1024 - kg };
        float cjs[4] = { 1.f, -1.f, 1.f, -1.f };   // conj flags for S~
#pragma unroll
        for (int o = 0; o < 4; ++o) {
            int kk = kks[o];
            float cg = cjs[o];
            float c1 = g_cos_tab[kk], s1 = g_msin_tab[kk];
            float c2 = c1 * c1 - s1 * s1, s2 = 2.f * c1 * s1;
            float c3 = c1 * c2 - s1 * s2, s3 = c1 * s2 + s1 * c2;
            // S~i = cg * Si
            float i0x = cg * Si[0].x, i0y = cg * Si[0].y;
            float i1x = cg * Si[1].x, i1y = cg * Si[1].y;
            float i2x = cg * Si[2].x, i2y = cg * Si[2].y;
            float i3x = cg * Si[3].x, i3y = cg * Si[3].y;
            float urx = Sr[0].x + c1 * Sr[1].x - s1 * i1x
                                + c2 * Sr[2].x - s2 * i2x
                                + c3 * Sr[3].x - s3 * i3x;
            float ury = Sr[0].y + c1 * Sr[1].y - s1 * i1y
                                + c2 * Sr[2].y - s2 * i2y
                                + c3 * Sr[3].y - s3 * i3y;
            float uix = i0x + c1 * i1x + s1 * Sr[1].x
                            + c2 * i2x + s2 * Sr[2].x
                            + c3 * i3x + s3 * Sr[3].x;
            float uiy = i0y + c1 * i1y + s1 * Sr[1].y
                            + c2 * i2y + s2 * Sr[2].y
                            + c3 * i3y + s3 * Sr[3].y;
            *(__half2*)(g_Uh + (size_t)kk * NJ + jg)        = __floats2half2_rn(urx, ury);
            *(__half2*)(g_Uh + (size_t)(KF + kk) * NJ + jg) = __floats2half2_rn(uix, uiy);
        }
    }
}

// ============================ combine (4 t's per lane, shfl halo, smem bounce) ============================
__device__ __forceinline__ void unpack8(uint2 a, uint2 b, float* d) {
    float2 f;
    f = __half22float2(*(__half2*)&a.x); d[0] = f.x; d[1] = f.y;
    f = __half22float2(*(__half2*)&a.y); d[2] = f.x; d[3] = f.y;
    f = __half22float2(*(__half2*)&b.x); d[4] = f.x; d[5] = f.y;
    f = __half22float2(*(__half2*)&b.y); d[6] = f.x; d[7] = f.y;
}

__global__ void __launch_bounds__(128) combine5_kernel(float* __restrict__ out) {
    __shared__ float sfr[4][2][128];
    __shared__ float sfi[4][2][128];
    const int bc   = blockIdx.z;
    const int lane = threadIdx.x;
    const int ty   = threadIdx.y;
    const int tbase = blockIdx.x * 128;
    const int kb   = (blockIdx.y * 4 + ty) * 32;
    if (kb > 1024) return;

    const int t4  = tbase + lane * 4;
    const int tt4 = (t4 <= 512) ? t4 : 512;
    const size_t jj = (size_t)bc * NSEG + tt4;
    const long baseT = (long)bc * KF;

    float pXr0[4], pXr1[4], pXi0[4], pXi1[4];
#pragma unroll
    for (int e = 0; e < 4; ++e) { pXr0[e] = pXr1[e] = pXi0[e] = pXi1[e] = 0.f; }

#pragma unroll 2
    for (int i = 0; i < 34; ++i) {
        int k = kb - 1 + i;
        int kk = k;
        float sgn = 1.f;
        if (kk < 0)         { kk = -kk;       sgn = -1.f; }
        else if (kk > 1024) { kk = 2048 - kk; sgn = -1.f; }

        const __half* pr = g_Uh + (size_t)kk * NJ + jj;
        const __half* pi = g_Uh + (size_t)(KF + kk) * NJ + jj;
        uint2 vr_ = *(const uint2*)pr;
        uint2 vi_ = *(const uint2*)pi;
        uint2 vrn, vin;
        vrn.x = __shfl_down_sync(0xffffffffu, vr_.x, 1);
        vrn.y = __shfl_down_sync(0xffffffffu, vr_.y, 1);
        vin.x = __shfl_down_sync(0xffffffffu, vi_.x, 1);
        vin.y = __shfl_down_sync(0xffffffffu, vi_.y, 1);
        if (lane == 31) {
            vrn = *(const uint2*)(pr + 4);
            vin = *(const uint2*)(pi + 4);
        }
        float rr[8], ii[8];
        unpack8(vr_, vrn, rr);
        unpack8(vi_, vin, ii);

        float xr[4], xi[4];
        switch (kk & 3) {
            case 0:
#pragma unroll
                for (int e = 0; e < 4; ++e) {
                    xr[e] = rr[e] + rr[e+1] + rr[e+2] + rr[e+3];
                    xi[e] = sgn * (ii[e] + ii[e+1] + ii[e+2] + ii[e+3]);
                }
                break;
            case 1:
#pragma unroll
                for (int e = 0; e < 4; ++e) {
                    xr[e] = rr[e] + ii[e+1] - rr[e+2] - ii[e+3];
                    xi[e] = sgn * (ii[e] - rr[e+1] - ii[e+2] + rr[e+3]);
                }
                break;
            case 2:
#pragma unroll
                for (int e = 0; e < 4; ++e) {
                    xr[e] = rr[e] - rr[e+1] + rr[e+2] - rr[e+3];
                    xi[e] = sgn * (ii[e] - ii[e+1] + ii[e+2] - ii[e+3]);
                }
                break;
            default:
#pragma unroll
                for (int e = 0; e < 4; ++e) {
                    xr[e] = rr[e] - ii[e+1] - rr[e+2] + ii[e+3];
                    xi[e] = sgn * (ii[e] + rr[e+1] - ii[e+2] - rr[e+3]);
                }
                break;
        }

        if (i >= 2) {
            const int ko = k - 1;
            const int buf = i & 1;
            float4 vr, vi;
            vr.x = 0.5f * pXr1[0] - 0.25f * (pXr0[0] + xr[0]);
            vr.y = 0.5f * pXr1[1] - 0.25f * (pXr0[1] + xr[1]);
            vr.z = 0.5f * pXr1[2] - 0.25f * (pXr0[2] + xr[2]);
            vr.w = 0.5f * pXr1[3] - 0.25f * (pXr0[3] + xr[3]);
            vi.x = 0.5f * pXi1[0] - 0.25f * (pXi0[0] + xi[0]);
            vi.y = 0.5f * pXi1[1] - 0.25f * (pXi0[1] + xi[1]);
            vi.z = 0.5f * pXi1[2] - 0.25f * (pXi0[2] + xi[2]);
            vi.w = 0.5f * pXi1[3] - 0.25f * (pXi0[3] + xi[3]);
            *(float4*)&sfr[ty][buf][lane * 4] = vr;
            *(float4*)&sfi[ty][buf][lane * 4] = vi;
            __syncwarp();
            if (ko <= 1024) {
                const long baseR = (baseT + ko) * NT;
#pragma unroll
                for (int e = 0; e < 4; ++e) {
                    int t = tbase + 32 * e + lane;
                    if (t <= 512) {
                        out[baseR + t]            = sfr[ty][buf][32 * e + lane];
                        out[IMAG_OFF + baseR + t] = sfi[ty][buf][32 * e + lane];
                    }
                }
            }
        }
#pragma unroll
        for (int e = 0; e < 4; ++e) {
            pXr0[e] = pXr1[e]; pXr1[e] = xr[e];
            pXi0[e] = pXi1[e]; pXi1[e] = xi[e];
        }
    }
}

// ============================ launch ============================
extern "C" void kernel_launch(void* const* d_in, const int* in_sizes, int n_in,
                              void* d_out, int out_size)
{
    const float* x = (const float*)d_in[0];
    float* out = (float*)d_out;

    cudaFuncSetAttribute(gemm_mma_kernel,
                         cudaFuncAttributeMaxDynamicSharedMemorySize, GEMM_SMEM);

    prep_kernel<<<PREP_GRID, 256>>>(x);
    gemm_mma_kernel<<<dim3(NJ / 64, MROWSA / 64), 256, GEMM_SMEM>>>();
    combine5_kernel<<<dim3(5, 9, NBC), dim3(32, 4)>>>(out);
}